// round 9
// baseline (speedup 1.0000x reference)
#include <cuda_runtime.h>
#include <cstddef>

// Problem constants (fixed shapes from setup_inputs)
#define C_    32
#define H_    192
#define W_    256
#define S_    9
#define G_    8
#define HW_   (H_*W_)            // 49152
#define HWS_  ((size_t)HW_*S_)   // 442368
#define CHWS_ ((size_t)C_*HWS_)

#define TPB   64
#define NSPL  2                  // split of the 8 source images across blockIdx.y
#define NPER  (8/NSPL)           // images per CTA

__device__ float g_M[C_*C_];     // Wp^T Wp (symmetric)
__device__ float g_v[C_];        // Wp^T bp

// ---------------- prep: M = Wp^T Wp, v = Wp^T bp ----------------
__global__ void prep_kernel(const float* __restrict__ Wp, const float* __restrict__ bp) {
    int tid = threadIdx.x;            // 1024 threads
    int i = tid >> 5, j = tid & 31;
    float m = 0.f;
    #pragma unroll
    for (int d = 0; d < C_; d++) m += Wp[d*C_ + i] * Wp[d*C_ + j];
    g_M[i*C_ + j] = m;
    if (tid < C_) {
        float vv = 0.f;
        #pragma unroll
        for (int d = 0; d < C_; d++) vv += Wp[d*C_ + tid] * bp[d];
        g_v[tid] = vv;
    }
}

// ---------------- main fused kernel ----------------
// Thread-per-pixel (coalescing-correct: warp spans 32 consecutive p).
// blockIdx.y selects a half of the source images -> 2x grid, 2x warps/SM.
// Pass-1 duplicated across the y-pair; second read is L2-hot.
__global__ void __launch_bounds__(TPB, 10)
main_kernel(const float* __restrict__ f, float* __restrict__ out) {
    const int p  = blockIdx.x * TPB + threadIdx.x;   // pixel index h*W + w
    const int n0 = blockIdx.y * NPER;                // first source image (0-based among 8)
    const float* __restrict__ refp = f + (size_t)p * S_;

    // ---- 1. r_mid (s=4) for all 32 channels ----
    float rm[C_];
    #pragma unroll
    for (int c = 0; c < C_; c++) rm[c] = __ldg(refp + (size_t)c * HWS_ + 4);

    // ---- 2. logits: l[s] = sum_c (M rm + v)[c] * r[c][s]  (tv folded) ----
    float l[S_];
    #pragma unroll
    for (int s = 0; s < S_; s++) l[s] = 0.f;

    const float4* __restrict__ M4 = (const float4*)g_M;
    #pragma unroll 4
    for (int c = 0; c < C_; c++) {
        float tvc = g_v[c];
        #pragma unroll
        for (int q = 0; q < C_/4; q++) {
            float4 m4 = M4[c*(C_/4) + q];
            tvc += m4.x*rm[4*q] + m4.y*rm[4*q+1] + m4.z*rm[4*q+2] + m4.w*rm[4*q+3];
        }
        const float* rp = refp + (size_t)c * HWS_;
        #pragma unroll
        for (int s = 0; s < S_; s++) l[s] += tvc * __ldg(rp + s);
    }

    // ---- 3. softmax over s (shift-invariant terms dropped) ----
    const float inv_sqrtC = 0.17677669529663687f;   // 1/sqrt(32)
    float mx = l[0];
    #pragma unroll
    for (int s = 1; s < S_; s++) mx = fmaxf(mx, l[s]);
    float att[S_], sum = 0.f;
    #pragma unroll
    for (int s = 0; s < S_; s++) { att[s] = __expf((l[s] - mx) * inv_sqrtC); sum += att[s]; }
    const float isum = __frcp_rn(sum);
    #pragma unroll
    for (int s = 0; s < S_; s++) att[s] *= isum;

    // ---- 4. stream this CTA's half of the sources; ref rescaled on the fly ----
    #pragma unroll 1
    for (int g = 0; g < G_; g++) {
        float acc[NPER];
        #pragma unroll
        for (int n = 0; n < NPER; n++) acc[n] = 0.f;
        #pragma unroll 1
        for (int cc = 0; cc < 4; cc++) {
            const int c = g*4 + cc;
            const float* rp = refp + (size_t)c * HWS_;
            float w[S_];
            #pragma unroll
            for (int s = 0; s < S_; s++) w[s] = __ldg(rp + s) * att[s];
            #pragma unroll
            for (int n = 0; n < NPER; n++) {
                const float* __restrict__ sp =
                    f + (size_t)(n0 + n + 1)*CHWS_ + (size_t)c*HWS_ + (size_t)p*S_;
                float a = 0.f;
                #pragma unroll
                for (int s = 0; s < S_; s++) a += w[s] * __ldcs(sp + s);
                acc[n] += a;
            }
        }
        #pragma unroll
        for (int n = 0; n < NPER; n++)
            out[(size_t)((n0 + n)*G_ + g)*HW_ + p] = acc[n];
    }
}

extern "C" void kernel_launch(void* const* d_in, const int* in_sizes, int n_in,
                              void* d_out, int out_size) {
    // Identify inputs by element count: f = 127401984, Wp = 1024, bp = 32
    const float* f  = nullptr;
    const float* Wp = nullptr;
    const float* bp = nullptr;
    for (int i = 0; i < n_in; i++) {
        if      (in_sizes[i] == 127401984) f  = (const float*)d_in[i];
        else if (in_sizes[i] == 1024)      Wp = (const float*)d_in[i];
        else if (in_sizes[i] == 32)        bp = (const float*)d_in[i];
    }
    if (!f || !Wp || !bp) {  // fallback positional
        f  = (const float*)d_in[0];
        Wp = (const float*)d_in[1];
        bp = (const float*)d_in[2];
    }
    float* out = (float*)d_out;

    prep_kernel<<<1, 1024>>>(Wp, bp);
    dim3 grid(HW_/TPB, NSPL);
    main_kernel<<<grid, TPB>>>(f, out);
}

// round 10
// speedup vs baseline: 1.0889x; 1.0889x over previous
#include <cuda_runtime.h>
#include <cstddef>

// Problem constants (fixed shapes from setup_inputs)
#define C_    32
#define H_    192
#define W_    256
#define S_    9
#define G_    8
#define HW_   (H_*W_)            // 49152
#define HWS_  ((size_t)HW_*S_)   // 442368
#define CHWS_ ((size_t)C_*HWS_)

#define TPB   64
#define NSPL  2                  // source-image split across blockIdx.y in kernel B
#define NPER  (8/NSPL)           // images per CTA in kernel B

__device__ float g_M[C_*C_];          // Wp^T Wp (symmetric)
__device__ float g_v[C_];             // Wp^T bp
__device__ float g_att[S_ * HW_];     // att scratch, SoA: [s][p] (coalesced)

// ---------------- prep: M = Wp^T Wp, v = Wp^T bp ----------------
__global__ void prep_kernel(const float* __restrict__ Wp, const float* __restrict__ bp) {
    int tid = threadIdx.x;            // 1024 threads
    int i = tid >> 5, j = tid & 31;
    float m = 0.f;
    #pragma unroll
    for (int d = 0; d < C_; d++) m += Wp[d*C_ + i] * Wp[d*C_ + j];
    g_M[i*C_ + j] = m;
    if (tid < C_) {
        float vv = 0.f;
        #pragma unroll
        for (int d = 0; d < C_; d++) vv += Wp[d*C_ + tid] * bp[d];
        g_v[tid] = vv;
    }
}

// ---------------- kernel A: attention weights per pixel ----------------
__global__ void __launch_bounds__(TPB, 10)
att_kernel(const float* __restrict__ f) {
    const int p = blockIdx.x * TPB + threadIdx.x;   // pixel index h*W + w
    const float* __restrict__ refp = f + (size_t)p * S_;

    // r_mid (s=4) for all 32 channels
    float rm[C_];
    #pragma unroll
    for (int c = 0; c < C_; c++) rm[c] = __ldg(refp + (size_t)c * HWS_ + 4);

    // logits: l[s] = sum_c (M rm + v)[c] * r[c][s]
    float l[S_];
    #pragma unroll
    for (int s = 0; s < S_; s++) l[s] = 0.f;

    const float4* __restrict__ M4 = (const float4*)g_M;
    #pragma unroll 4
    for (int c = 0; c < C_; c++) {
        float tvc = g_v[c];
        #pragma unroll
        for (int q = 0; q < C_/4; q++) {
            float4 m4 = M4[c*(C_/4) + q];
            tvc += m4.x*rm[4*q] + m4.y*rm[4*q+1] + m4.z*rm[4*q+2] + m4.w*rm[4*q+3];
        }
        const float* rp = refp + (size_t)c * HWS_;
        #pragma unroll
        for (int s = 0; s < S_; s++) l[s] += tvc * __ldg(rp + s);
    }

    // softmax over s (shift-invariant terms dropped)
    const float inv_sqrtC = 0.17677669529663687f;   // 1/sqrt(32)
    float mx = l[0];
    #pragma unroll
    for (int s = 1; s < S_; s++) mx = fmaxf(mx, l[s]);
    float e[S_], sum = 0.f;
    #pragma unroll
    for (int s = 0; s < S_; s++) { e[s] = __expf((l[s] - mx) * inv_sqrtC); sum += e[s]; }
    const float isum = __frcp_rn(sum);
    #pragma unroll
    for (int s = 0; s < S_; s++) g_att[s * HW_ + p] = e[s] * isum;
}

// ---------------- kernel B: stream sources (n-split, no prologue to duplicate) ----------------
__global__ void __launch_bounds__(TPB, 16)
stream_kernel(const float* __restrict__ f, float* __restrict__ out) {
    const int p  = blockIdx.x * TPB + threadIdx.x;  // pixel index h*W + w
    const int n0 = blockIdx.y * NPER;               // first source image for this CTA
    const float* __restrict__ refp = f + (size_t)p * S_;

    // load att[9] (coalesced SoA)
    float att[S_];
    #pragma unroll
    for (int s = 0; s < S_; s++) att[s] = __ldg(&g_att[s * HW_ + p]);

    #pragma unroll 1
    for (int g = 0; g < G_; g++) {
        float acc[NPER];
        #pragma unroll
        for (int n = 0; n < NPER; n++) acc[n] = 0.f;
        #pragma unroll 1
        for (int cc = 0; cc < 4; cc++) {
            const int c = g*4 + cc;
            const float* rp = refp + (size_t)c * HWS_;
            float w[S_];
            #pragma unroll
            for (int s = 0; s < S_; s++) w[s] = __ldg(rp + s) * att[s];
            #pragma unroll
            for (int n = 0; n < NPER; n++) {
                const float* __restrict__ sp =
                    f + (size_t)(n0 + n + 1)*CHWS_ + (size_t)c*HWS_ + (size_t)p*S_;
                float a = 0.f;
                #pragma unroll
                for (int s = 0; s < S_; s++) a += w[s] * __ldcs(sp + s);
                acc[n] += a;
            }
        }
        #pragma unroll
        for (int n = 0; n < NPER; n++)
            out[(size_t)((n0 + n)*G_ + g)*HW_ + p] = acc[n];
    }
}

extern "C" void kernel_launch(void* const* d_in, const int* in_sizes, int n_in,
                              void* d_out, int out_size) {
    // Identify inputs by element count: f = 127401984, Wp = 1024, bp = 32
    const float* f  = nullptr;
    const float* Wp = nullptr;
    const float* bp = nullptr;
    for (int i = 0; i < n_in; i++) {
        if      (in_sizes[i] == 127401984) f  = (const float*)d_in[i];
        else if (in_sizes[i] == 1024)      Wp = (const float*)d_in[i];
        else if (in_sizes[i] == 32)        bp = (const float*)d_in[i];
    }
    if (!f || !Wp || !bp) {  // fallback positional
        f  = (const float*)d_in[0];
        Wp = (const float*)d_in[1];
        bp = (const float*)d_in[2];
    }
    float* out = (float*)d_out;

    prep_kernel<<<1, 1024>>>(Wp, bp);
    att_kernel<<<HW_/TPB, TPB>>>(f);
    dim3 gridB(HW_/TPB, NSPL);
    stream_kernel<<<gridB, TPB>>>(f, out);
}